// round 1
// baseline (speedup 1.0000x reference)
#include <cuda_runtime.h>
#include <cuda_bf16.h>
#include <cstdint>

// Problem constants
#define BATCH 256
#define TLEN  500
#define IDIM  1024   // K
#define ODIM  2048   // N
#define TEFF  (TLEN - 1)            // 499 : only h[:, :T-1, :] is consumed
#define MEFF  (BATCH * TEFF)        // 127744 = 998 * 128 exactly

// GEMM tiling
#define BM 128
#define BN 128
#define BK 16
#define TM 8
#define TN 8
// 256 threads per CTA

// Kernel 1: h = x @ w, written into out shifted by one timestep:
//   out[b, t+1, :] = h[b, t, :]   for t in [0, T-2]
// (out[b,0,:] is written by the scan kernel as zeros.)
__global__ __launch_bounds__(256, 2)
void synaptic_gemm_kernel(const float* __restrict__ x,
                          const float* __restrict__ w,
                          float* __restrict__ out)
{
    __shared__ float As[BK][BM];
    __shared__ float Bs[BK][BN];

    const int tile_n = blockIdx.x;       // 0..15
    const int tile_m = blockIdx.y;       // 0..997
    const int tid    = threadIdx.x;      // 0..255

    const int row0 = tile_m * BM;

    // thread micro-tile coordinates
    const int tm = (tid >> 4) * TM;      // 0..120
    const int tn = (tid & 15) * TN;      // 0..120

    float acc[TM][TN];
#pragma unroll
    for (int i = 0; i < TM; i++)
#pragma unroll
        for (int j = 0; j < TN; j++)
            acc[i][j] = 0.f;

    // ---- A-load indexing: 128 rows x 16 cols = 512 float4; 2 per thread ----
    // f = tid + 256*i ; r = f>>2 (row 0..127) ; col = (f&3)*4  (f&3 == tid&3)
    int a_r[2];
    size_t a_src[2];
    const int acol0 = (tid & 3) * 4;
#pragma unroll
    for (int i = 0; i < 2; i++) {
        int f = tid + i * 256;
        int r = f >> 2;                  // 0..127
        int gr = row0 + r;               // effective row (always < MEFF, exact grid)
        int b  = gr / TEFF;
        int t  = gr - b * TEFF;
        a_r[i]   = r;
        a_src[i] = (size_t)(b * TLEN + t) * IDIM;
    }

    // ---- B-load indexing: 16 rows x 128 cols = 512 float4; 2 per thread ----
    const int bcol0 = (tid & 31) * 4;
    const int brow0 = (tid >> 5);        // 0..7 ; second load at +8
    const float* wptr = w + (size_t)tile_n * BN;

    for (int k0 = 0; k0 < IDIM; k0 += BK) {
        // load A (transpose into SMEM)
#pragma unroll
        for (int i = 0; i < 2; i++) {
            float4 v = *(const float4*)(x + a_src[i] + k0 + acol0);
            As[acol0 + 0][a_r[i]] = v.x;
            As[acol0 + 1][a_r[i]] = v.y;
            As[acol0 + 2][a_r[i]] = v.z;
            As[acol0 + 3][a_r[i]] = v.w;
        }
        // load B
#pragma unroll
        for (int i = 0; i < 2; i++) {
            int br = brow0 + i * 8;
            float4 v = *(const float4*)(wptr + (size_t)(k0 + br) * ODIM + bcol0);
            *(float4*)&Bs[br][bcol0] = v;
        }
        __syncthreads();

#pragma unroll
        for (int k = 0; k < BK; k++) {
            float a[TM], bb[TN];
#pragma unroll
            for (int i = 0; i < TM; i++) a[i] = As[k][tm + i];
#pragma unroll
            for (int j = 0; j < TN; j++) bb[j] = Bs[k][tn + j];
#pragma unroll
            for (int i = 0; i < TM; i++)
#pragma unroll
                for (int j = 0; j < TN; j++)
                    acc[i][j] = fmaf(a[i], bb[j], acc[i][j]);
        }
        __syncthreads();
    }

    // ---- store: out[b, t+1, tile_n*BN + tn + j] ----
#pragma unroll
    for (int i = 0; i < TM; i++) {
        int gr = row0 + tm + i;
        int b  = gr / TEFF;
        int t  = gr - b * TEFF;
        float* dst = out + ((size_t)(b * TLEN + t + 1)) * ODIM + tile_n * BN + tn;
        float4 v0 = make_float4(acc[i][0], acc[i][1], acc[i][2], acc[i][3]);
        float4 v1 = make_float4(acc[i][4], acc[i][5], acc[i][6], acc[i][7]);
        *(float4*)(dst)     = v0;
        *(float4*)(dst + 4) = v1;
    }
}

// Kernel 2: in-place leaky-integrator scan over time.
// out currently holds h shifted by one step; after this kernel:
//   out[b,0,:] = 0 ; out[b,t,:] = decay*out[b,t-1,:] + h[b,t-1,:]
__global__ __launch_bounds__(256)
void synaptic_scan_kernel(float* __restrict__ out,
                          const float* __restrict__ alpha,
                          const float* __restrict__ beta)
{
    const int o = blockIdx.x * blockDim.x + threadIdx.x;   // 0..2047
    const int b = blockIdx.y;                              // 0..255
    const float decay = alpha[o] * (1.0f - beta[o]);

    float* p = out + (size_t)b * TLEN * ODIM + o;
    p[0] = 0.0f;
    float syn = 0.0f;
#pragma unroll 4
    for (int t = 1; t < TLEN; t++) {
        float v = p[(size_t)t * ODIM];
        syn = fmaf(decay, syn, v);
        p[(size_t)t * ODIM] = syn;
    }
}

extern "C" void kernel_launch(void* const* d_in, const int* in_sizes, int n_in,
                              void* d_out, int out_size)
{
    const float* x     = (const float*)d_in[0];   // [B, T, I]
    const float* w     = (const float*)d_in[1];   // [I, O]
    const float* alpha = (const float*)d_in[2];   // [1, O]
    const float* beta  = (const float*)d_in[3];   // [1, O]
    float* out = (float*)d_out;                   // [B, T, O]

    dim3 ggrid(ODIM / BN, MEFF / BM);             // (16, 998)
    synaptic_gemm_kernel<<<ggrid, 256>>>(x, w, out);

    dim3 sgrid(ODIM / 256, BATCH);                // (8, 256)
    synaptic_scan_kernel<<<sgrid, 256>>>(out, alpha, beta);
}

// round 3
// speedup vs baseline: 3.1397x; 3.1397x over previous
#include <cuda_runtime.h>
#include <cuda_bf16.h>
#include <cstdint>

// ---------------- Problem constants ----------------
#define BATCH 256
#define TLEN  500
#define IDIM  1024
#define ODIM  2048
#define TEFF  (TLEN - 1)            // 499
#define MEFF  (BATCH * TEFF)        // 127744 = 998 * 128
#define K3    (3 * IDIM)            // 3072 : [x_hi | x_lo | x_hi] vs [w_hi | w_hi | w_lo]

// ---------------- GEMM tiling ----------------
#define BM 128
#define BN 128
#define BK 32
#define NST 4
#define NITER (K3 / BK)             // 96
#define ROWP  (BK + 8)              // padded row stride in halves (40) -> conflict-free ldmatrix
#define A_STAGE_HALFS (BM * ROWP)   // 5120
#define B_STAGE_HALFS (BN * ROWP)   // 5120
#define STAGE_BYTES   ((A_STAGE_HALFS + B_STAGE_HALFS) * 2)   // 20480
#define SMEM_TOTAL    (NST * STAGE_BYTES)                     // 81920

// ---------------- Scratch (device globals; no runtime alloc) ----------------
__device__ __align__(256) __nv_bfloat16 g_A3[(size_t)MEFF * K3]; // ~785 MB
__device__ __align__(256) __nv_bfloat16 g_B3[(size_t)ODIM * K3]; // ~12.6 MB

// ---------------- PTX helpers ----------------
__device__ __forceinline__ uint32_t smem_u32(const void* p) {
    uint32_t a;
    asm("{ .reg .u64 t; cvta.to.shared.u64 t, %1; cvt.u32.u64 %0, t; }" : "=r"(a) : "l"(p));
    return a;
}
__device__ __forceinline__ void cp_async16(uint32_t dst, const void* src) {
    asm volatile("cp.async.cg.shared.global [%0], [%1], 16;" :: "r"(dst), "l"(src));
}
__device__ __forceinline__ void cp_commit() {
    asm volatile("cp.async.commit_group;" ::: "memory");
}
__device__ __forceinline__ void ldmatrix_x4(uint32_t& r0, uint32_t& r1, uint32_t& r2, uint32_t& r3,
                                            uint32_t addr) {
    asm volatile("ldmatrix.sync.aligned.m8n8.x4.shared.b16 {%0,%1,%2,%3}, [%4];"
                 : "=r"(r0), "=r"(r1), "=r"(r2), "=r"(r3) : "r"(addr));
}
__device__ __forceinline__ void mma_16816(float& c0, float& c1, float& c2, float& c3,
                                          uint32_t a0, uint32_t a1, uint32_t a2, uint32_t a3,
                                          uint32_t b0, uint32_t b1) {
    asm volatile(
        "mma.sync.aligned.m16n8k16.row.col.f32.bf16.bf16.f32 "
        "{%0,%1,%2,%3}, {%4,%5,%6,%7}, {%8,%9}, {%0,%1,%2,%3};"
        : "+f"(c0), "+f"(c1), "+f"(c2), "+f"(c3)
        : "r"(a0), "r"(a1), "r"(a2), "r"(a3), "r"(b0), "r"(b1));
}

// ---------------- Conversion kernels ----------------
__device__ __forceinline__ uint32_t pack_bf2(float a, float b) {
    __nv_bfloat16 ha = __float2bfloat16(a), hb = __float2bfloat16(b);
    return (uint32_t)__bfloat16_as_ushort(ha) | ((uint32_t)__bfloat16_as_ushort(hb) << 16);
}

// x [B,T,I] f32 -> g_A3 rows [MEFF][K3]: [hi | lo | hi], row = b*TEFF + t (t < TEFF)
__global__ __launch_bounds__(256) void convert_x_kernel(const float* __restrict__ x) {
    const int row = blockIdx.x;
    const int b = row / TEFF;
    const int t = row - b * TEFF;
    const float4 v = ((const float4*)(x + ((size_t)(b * TLEN + t)) * IDIM))[threadIdx.x];
    __nv_bfloat16* dst = g_A3 + (size_t)row * K3 + threadIdx.x * 4;

    float h0 = __bfloat162float(__float2bfloat16(v.x));
    float h1 = __bfloat162float(__float2bfloat16(v.y));
    float h2 = __bfloat162float(__float2bfloat16(v.z));
    float h3 = __bfloat162float(__float2bfloat16(v.w));

    uint2 hi = make_uint2(pack_bf2(v.x, v.y), pack_bf2(v.z, v.w));
    uint2 lo = make_uint2(pack_bf2(v.x - h0, v.y - h1), pack_bf2(v.z - h2, v.w - h3));

    *(uint2*)(dst)            = hi;
    *(uint2*)(dst + IDIM)     = lo;
    *(uint2*)(dst + 2 * IDIM) = hi;
}

// w [I,O] f32 -> g_B3 rows [ODIM][K3] (K-major): [hi | hi | lo]
__global__ __launch_bounds__(256) void convert_w_kernel(const float* __restrict__ w) {
    const size_t idx = (size_t)blockIdx.x * 256 + threadIdx.x;  // k*ODIM + n
    const int k = (int)(idx >> 11);
    const int n = (int)(idx & (ODIM - 1));
    const float v = w[idx];
    __nv_bfloat16 h = __float2bfloat16(v);
    __nv_bfloat16 l = __float2bfloat16(v - __bfloat162float(h));
    __nv_bfloat16* dst = g_B3 + (size_t)n * K3 + k;
    dst[0]        = h;
    dst[IDIM]     = h;
    dst[2 * IDIM] = l;
}

// ---------------- HMMA GEMM ----------------
// out[b, t+1, n] = sum_k A3[row][k] * B3[n][k],  row = b*TEFF + t
extern __shared__ __nv_bfloat16 smem[];

__device__ __forceinline__ void load_stage(int tid, int m0, int n0, int kidx, int stage,
                                           uint32_t sbase) {
    const uint32_t sA = sbase + stage * STAGE_BYTES;
    const uint32_t sB = sA + A_STAGE_HALFS * 2;
    const int k0 = kidx * BK;
    // A: 128 rows x 32 halves = 512 x 16B chunks ; each thread 2
#pragma unroll
    for (int q = 0; q < 2; q++) {
        int idx = tid + q * 256;
        int r = idx >> 2, c = idx & 3;               // row 0..127, chunk 0..3 (8 halves each)
        const void* g = (const void*)(g_A3 + (size_t)(m0 + r) * K3 + k0 + c * 8);
        cp_async16(sA + (r * ROWP + c * 8) * 2, g);
    }
#pragma unroll
    for (int q = 0; q < 2; q++) {
        int idx = tid + q * 256;
        int r = idx >> 2, c = idx & 3;
        const void* g = (const void*)(g_B3 + (size_t)(n0 + r) * K3 + k0 + c * 8);
        cp_async16(sB + (r * ROWP + c * 8) * 2, g);
    }
}

__global__ __launch_bounds__(256, 2)
void synaptic_hmma_gemm(float* __restrict__ out) {
    const int tid = threadIdx.x;
    const int wid = tid >> 5;
    const int lane = tid & 31;
    const int warp_m = wid & 1;     // 2 warps along M (64 each)
    const int warp_n = wid >> 1;    // 4 warps along N (32 each)
    const int n0 = blockIdx.x * BN;
    const int m0 = blockIdx.y * BM;

    const uint32_t sbase = smem_u32(smem);

    float acc[4][4][4];             // [m-tile][n-tile][frag]
#pragma unroll
    for (int i = 0; i < 4; i++)
#pragma unroll
        for (int j = 0; j < 4; j++)
#pragma unroll
            for (int f = 0; f < 4; f++) acc[i][j][f] = 0.f;

    // ldmatrix per-lane base offsets (halves) within a stage
    const int lrow = lane & 15;
    const int lk   = (lane >> 4) * 8;
    const uint32_t a_base = (uint32_t)((warp_m * 64 + lrow) * ROWP + lk) * 2;
    const uint32_t b_base = (uint32_t)((warp_n * 32 + lrow) * ROWP + lk) * 2
                            + (uint32_t)A_STAGE_HALFS * 2;

    // prologue: fill NST-1 stages
#pragma unroll
    for (int s = 0; s < NST - 1; s++) {
        load_stage(tid, m0, n0, s, s, sbase);
        cp_commit();
    }

    for (int it = 0; it < NITER; it++) {
        const int s = it & (NST - 1);
        asm volatile("cp.async.wait_group %0;" :: "n"(NST - 2) : "memory");
        __syncthreads();

        // prefetch next stage
        if (it + NST - 1 < NITER)
            load_stage(tid, m0, n0, it + NST - 1, (it + NST - 1) & (NST - 1), sbase);
        cp_commit();

        const uint32_t sa = sbase + s * STAGE_BYTES + a_base;
        const uint32_t sb = sbase + s * STAGE_BYTES + b_base;

#pragma unroll
        for (int kk = 0; kk < BK; kk += 16) {
            uint32_t a[4][4], b[2][4];
#pragma unroll
            for (int mt = 0; mt < 4; mt++)
                ldmatrix_x4(a[mt][0], a[mt][1], a[mt][2], a[mt][3],
                            sa + (mt * 16 * ROWP + kk) * 2);
#pragma unroll
            for (int np = 0; np < 2; np++)
                ldmatrix_x4(b[np][0], b[np][1], b[np][2], b[np][3],
                            sb + (np * 16 * ROWP + kk) * 2);
#pragma unroll
            for (int mt = 0; mt < 4; mt++) {
#pragma unroll
                for (int nt = 0; nt < 4; nt++) {
                    // n-tile nt: pair (np = nt>>1), mats {r0,r2} for even, {r1,r3} for odd
                    const int np = nt >> 1, odd = nt & 1;
                    mma_16816(acc[mt][nt][0], acc[mt][nt][1], acc[mt][nt][2], acc[mt][nt][3],
                              a[mt][0], a[mt][1], a[mt][2], a[mt][3],
                              b[np][odd], b[np][2 + odd]);
                }
            }
        }
        __syncthreads();
    }

    // ---- epilogue: out[b, t+1, col] ----
    const int r_lo = lane >> 2;
    const int c_lo = (lane & 3) * 2;
#pragma unroll
    for (int mt = 0; mt < 4; mt++) {
#pragma unroll
        for (int half = 0; half < 2; half++) {
            const int gr = m0 + warp_m * 64 + mt * 16 + r_lo + half * 8;
            const int b = gr / TEFF;
            const int t = gr - b * TEFF;
            float* obase = out + ((size_t)(b * TLEN + t + 1)) * ODIM
                               + n0 + warp_n * 32 + c_lo;
#pragma unroll
            for (int nt = 0; nt < 4; nt++) {
                float2 v;
                v.x = acc[mt][nt][half * 2 + 0];
                v.y = acc[mt][nt][half * 2 + 1];
                *(float2*)(obase + nt * 8) = v;
            }
        }
    }
}

// ---------------- Scan (in-place over time) ----------------
__global__ __launch_bounds__(256)
void synaptic_scan_kernel(float* __restrict__ out,
                          const float* __restrict__ alpha,
                          const float* __restrict__ beta) {
    const int o = blockIdx.x * blockDim.x + threadIdx.x;
    const int b = blockIdx.y;
    const float decay = alpha[o] * (1.0f - beta[o]);

    float* p = out + (size_t)b * TLEN * ODIM + o;
    p[0] = 0.0f;
    float syn = 0.0f;
#pragma unroll 4
    for (int t = 1; t < TLEN; t++) {
        float v = p[(size_t)t * ODIM];
        syn = fmaf(decay, syn, v);
        p[(size_t)t * ODIM] = syn;
    }
}

// ---------------- Launch ----------------
extern "C" void kernel_launch(void* const* d_in, const int* in_sizes, int n_in,
                              void* d_out, int out_size) {
    const float* x     = (const float*)d_in[0];
    const float* w     = (const float*)d_in[1];
    const float* alpha = (const float*)d_in[2];
    const float* beta  = (const float*)d_in[3];
    float* out = (float*)d_out;

    cudaFuncSetAttribute(synaptic_hmma_gemm, cudaFuncAttributeMaxDynamicSharedMemorySize,
                         SMEM_TOTAL);

    convert_w_kernel<<<(IDIM * ODIM) / 256, 256>>>(w);
    convert_x_kernel<<<MEFF, 256>>>(x);
    synaptic_hmma_gemm<<<dim3(ODIM / BN, MEFF / BM), 256, SMEM_TOTAL>>>(out);
    synaptic_scan_kernel<<<dim3(ODIM / 256, BATCH), 256>>>(out, alpha, beta);
}

// round 4
// speedup vs baseline: 8.1407x; 2.5928x over previous
#include <cuda_runtime.h>
#include <cuda_fp16.h>
#include <cstdint>

// ---------------- Problem constants ----------------
#define BATCH 256
#define TLEN  500
#define IDIM  1024
#define ODIM  2048
#define TEFF  (TLEN - 1)            // 499
#define MEFF  (BATCH * TEFF)        // 127744 = 998 * 128

// ---------------- GEMM tiling ----------------
#define BM 128
#define BN 128
#define BK 32
#define NST 4
#define NITER (IDIM / BK)           // 32
#define ROWP  (BK + 8)              // padded row stride in halves (40) -> conflict-free ldmatrix
#define A_STAGE_HALFS (BM * ROWP)   // 5120
#define B_STAGE_HALFS (BN * ROWP)   // 5120
#define STAGE_BYTES   ((A_STAGE_HALFS + B_STAGE_HALFS) * 2)   // 20480
#define SMEM_TOTAL    (NST * STAGE_BYTES)                     // 81920

// ---------------- Scratch (device globals; no runtime alloc) ----------------
__device__ __align__(256) __half g_Ah[(size_t)MEFF * IDIM];  // ~262 MB
__device__ __align__(256) __half g_Bh[(size_t)ODIM * IDIM];  // ~4 MB (L2-resident)

// ---------------- PTX helpers ----------------
__device__ __forceinline__ uint32_t smem_u32(const void* p) {
    uint32_t a;
    asm("{ .reg .u64 t; cvta.to.shared.u64 t, %1; cvt.u32.u64 %0, t; }" : "=r"(a) : "l"(p));
    return a;
}
__device__ __forceinline__ void cp_async16(uint32_t dst, const void* src) {
    asm volatile("cp.async.cg.shared.global [%0], [%1], 16;" :: "r"(dst), "l"(src));
}
__device__ __forceinline__ void cp_commit() {
    asm volatile("cp.async.commit_group;" ::: "memory");
}
__device__ __forceinline__ void ldmatrix_x4(uint32_t& r0, uint32_t& r1, uint32_t& r2, uint32_t& r3,
                                            uint32_t addr) {
    asm volatile("ldmatrix.sync.aligned.m8n8.x4.shared.b16 {%0,%1,%2,%3}, [%4];"
                 : "=r"(r0), "=r"(r1), "=r"(r2), "=r"(r3) : "r"(addr));
}
__device__ __forceinline__ void mma_16816(float& c0, float& c1, float& c2, float& c3,
                                          uint32_t a0, uint32_t a1, uint32_t a2, uint32_t a3,
                                          uint32_t b0, uint32_t b1) {
    asm volatile(
        "mma.sync.aligned.m16n8k16.row.col.f32.f16.f16.f32 "
        "{%0,%1,%2,%3}, {%4,%5,%6,%7}, {%8,%9}, {%0,%1,%2,%3};"
        : "+f"(c0), "+f"(c1), "+f"(c2), "+f"(c3)
        : "r"(a0), "r"(a1), "r"(a2), "r"(a3), "r"(b0), "r"(b1));
}

// ---------------- Conversion kernels ----------------
// x [B,T,I] f32 -> g_Ah rows [MEFF][IDIM] fp16, row = b*TEFF + t (t < TEFF)
__global__ __launch_bounds__(256) void convert_x_kernel(const float* __restrict__ x) {
    const int row = blockIdx.x;
    const int b = row / TEFF;
    const int t = row - b * TEFF;
    const float4 v = ((const float4*)(x + ((size_t)(b * TLEN + t)) * IDIM))[threadIdx.x];
    __half2 h01 = __float22half2_rn(make_float2(v.x, v.y));
    __half2 h23 = __float22half2_rn(make_float2(v.z, v.w));
    uint2 pk;
    pk.x = *(uint32_t*)&h01;
    pk.y = *(uint32_t*)&h23;
    *(uint2*)(g_Ah + (size_t)row * IDIM + threadIdx.x * 4) = pk;
}

// w [I,O] f32 -> g_Bh [ODIM][IDIM] fp16 (K-major / transposed)
__global__ __launch_bounds__(256) void convert_w_kernel(const float* __restrict__ w) {
    const size_t idx = (size_t)blockIdx.x * 256 + threadIdx.x;  // k*ODIM + n
    const int k = (int)(idx >> 11);
    const int n = (int)(idx & (ODIM - 1));
    g_Bh[(size_t)n * IDIM + k] = __float2half_rn(w[idx]);
}

// ---------------- HMMA GEMM ----------------
// out[b, t+1, n] = sum_k x[row][k] * w[k][n],  row = b*TEFF + t
extern __shared__ __half smem[];

__device__ __forceinline__ void load_stage(int tid, int m0, int n0, int kidx, int stage,
                                           uint32_t sbase) {
    const uint32_t sA = sbase + stage * STAGE_BYTES;
    const uint32_t sB = sA + A_STAGE_HALFS * 2;
    const int k0 = kidx * BK;
#pragma unroll
    for (int q = 0; q < 2; q++) {
        int idx = tid + q * 256;
        int r = idx >> 2, c = idx & 3;               // row 0..127, chunk 0..3 (8 halves each)
        const void* g = (const void*)(g_Ah + (size_t)(m0 + r) * IDIM + k0 + c * 8);
        cp_async16(sA + (r * ROWP + c * 8) * 2, g);
    }
#pragma unroll
    for (int q = 0; q < 2; q++) {
        int idx = tid + q * 256;
        int r = idx >> 2, c = idx & 3;
        const void* g = (const void*)(g_Bh + (size_t)(n0 + r) * IDIM + k0 + c * 8);
        cp_async16(sB + (r * ROWP + c * 8) * 2, g);
    }
}

__global__ __launch_bounds__(256, 2)
void synaptic_hmma_gemm(float* __restrict__ out) {
    const int tid = threadIdx.x;
    const int wid = tid >> 5;
    const int lane = tid & 31;
    const int warp_m = wid & 1;     // 2 warps along M (64 each)
    const int warp_n = wid >> 1;    // 4 warps along N (32 each)
    const int n0 = blockIdx.x * BN;
    const int m0 = blockIdx.y * BM;

    const uint32_t sbase = smem_u32(smem);

    float acc[4][4][4];
#pragma unroll
    for (int i = 0; i < 4; i++)
#pragma unroll
        for (int j = 0; j < 4; j++)
#pragma unroll
            for (int f = 0; f < 4; f++) acc[i][j][f] = 0.f;

    const int lrow = lane & 15;
    const int lk   = (lane >> 4) * 8;
    const uint32_t a_base = (uint32_t)((warp_m * 64 + lrow) * ROWP + lk) * 2;
    const uint32_t b_base = (uint32_t)((warp_n * 32 + lrow) * ROWP + lk) * 2
                            + (uint32_t)A_STAGE_HALFS * 2;

#pragma unroll
    for (int s = 0; s < NST - 1; s++) {
        load_stage(tid, m0, n0, s, s, sbase);
        cp_commit();
    }

    for (int it = 0; it < NITER; it++) {
        const int s = it & (NST - 1);
        asm volatile("cp.async.wait_group %0;" :: "n"(NST - 2) : "memory");
        __syncthreads();

        if (it + NST - 1 < NITER)
            load_stage(tid, m0, n0, it + NST - 1, (it + NST - 1) & (NST - 1), sbase);
        cp_commit();

        const uint32_t sa = sbase + s * STAGE_BYTES + a_base;
        const uint32_t sb = sbase + s * STAGE_BYTES + b_base;

#pragma unroll
        for (int kk = 0; kk < BK; kk += 16) {
            uint32_t a[4][4], b[2][4];
#pragma unroll
            for (int mt = 0; mt < 4; mt++)
                ldmatrix_x4(a[mt][0], a[mt][1], a[mt][2], a[mt][3],
                            sa + (mt * 16 * ROWP + kk) * 2);
#pragma unroll
            for (int np = 0; np < 2; np++)
                ldmatrix_x4(b[np][0], b[np][1], b[np][2], b[np][3],
                            sb + (np * 16 * ROWP + kk) * 2);
#pragma unroll
            for (int mt = 0; mt < 4; mt++) {
#pragma unroll
                for (int nt = 0; nt < 4; nt++) {
                    const int np = nt >> 1, odd = nt & 1;
                    mma_16816(acc[mt][nt][0], acc[mt][nt][1], acc[mt][nt][2], acc[mt][nt][3],
                              a[mt][0], a[mt][1], a[mt][2], a[mt][3],
                              b[np][odd], b[np][2 + odd]);
                }
            }
        }
        __syncthreads();
    }

    // ---- epilogue: out[b, t+1, col] ----
    const int r_lo = lane >> 2;
    const int c_lo = (lane & 3) * 2;
#pragma unroll
    for (int mt = 0; mt < 4; mt++) {
#pragma unroll
        for (int half = 0; half < 2; half++) {
            const int gr = m0 + warp_m * 64 + mt * 16 + r_lo + half * 8;
            const int b = gr / TEFF;
            const int t = gr - b * TEFF;
            float* obase = out + ((size_t)(b * TLEN + t + 1)) * ODIM
                               + n0 + warp_n * 32 + c_lo;
#pragma unroll
            for (int nt = 0; nt < 4; nt++) {
                float2 v;
                v.x = acc[mt][nt][half * 2 + 0];
                v.y = acc[mt][nt][half * 2 + 1];
                *(float2*)(obase + nt * 8) = v;
            }
        }
    }
}

// ---------------- Scan (in-place over time) ----------------
__global__ __launch_bounds__(256)
void synaptic_scan_kernel(float* __restrict__ out,
                          const float* __restrict__ alpha,
                          const float* __restrict__ beta) {
    const int o = blockIdx.x * blockDim.x + threadIdx.x;
    const int b = blockIdx.y;
    const float decay = alpha[o] * (1.0f - beta[o]);

    float* p = out + (size_t)b * TLEN * ODIM + o;
    p[0] = 0.0f;
    float syn = 0.0f;
#pragma unroll 4
    for (int t = 1; t < TLEN; t++) {
        float v = p[(size_t)t * ODIM];
        syn = fmaf(decay, syn, v);
        p[(size_t)t * ODIM] = syn;
    }
}

// ---------------- Launch ----------------
extern "C" void kernel_launch(void* const* d_in, const int* in_sizes, int n_in,
                              void* d_out, int out_size) {
    const float* x     = (const float*)d_in[0];
    const float* w     = (const float*)d_in[1];
    const float* alpha = (const float*)d_in[2];
    const float* beta  = (const float*)d_in[3];
    float* out = (float*)d_out;

    cudaFuncSetAttribute(synaptic_hmma_gemm, cudaFuncAttributeMaxDynamicSharedMemorySize,
                         SMEM_TOTAL);

    convert_w_kernel<<<(IDIM * ODIM) / 256, 256>>>(w);
    convert_x_kernel<<<MEFF, 256>>>(x);
    synaptic_hmma_gemm<<<dim3(ODIM / BN, MEFF / BM), 256, SMEM_TOTAL>>>(out);
    synaptic_scan_kernel<<<dim3(ODIM / 256, BATCH), 256>>>(out, alpha, beta);
}

// round 5
// speedup vs baseline: 9.6009x; 1.1794x over previous
#include <cuda_runtime.h>
#include <cuda_fp16.h>
#include <cstdint>

// ---------------- Problem constants ----------------
#define BATCH 256
#define TLEN  500
#define IDIM  1024
#define ODIM  2048
#define TEFF  (TLEN - 1)            // 499
#define MEFF  (BATCH * TEFF)        // 127744

// ---------------- GEMM tiling ----------------
#define BM 128
#define BN 128
#define BK 32
#define NST 4
#define NITER (IDIM / BK)           // 32
#define NCHUNK 4                    // ceil(499/128)
#define ROWP  (BK + 8)              // padded row stride in halves (40)
#define A_STAGE_HALFS (BM * ROWP)   // 5120
#define B_STAGE_HALFS (BN * ROWP)   // 5120
#define STAGE_BYTES   ((A_STAGE_HALFS + B_STAGE_HALFS) * 2)   // 20480
#define HSTRIDE 136                 // fp32 h-tile row stride (words)
#define SMEM_TOTAL    (NST * STAGE_BYTES)                     // 81920 (>= 128*136*4 = 69632)

// ---------------- Scratch (device globals; no runtime alloc) ----------------
__device__ __align__(256) __half g_Ah[(size_t)MEFF * IDIM];  // ~262 MB
__device__ __align__(256) __half g_Bh[(size_t)ODIM * IDIM];  // ~4 MB (L2-resident)

// ---------------- PTX helpers ----------------
__device__ __forceinline__ uint32_t smem_u32(const void* p) {
    uint32_t a;
    asm("{ .reg .u64 t; cvta.to.shared.u64 t, %1; cvt.u32.u64 %0, t; }" : "=r"(a) : "l"(p));
    return a;
}
__device__ __forceinline__ void cp_async16(uint32_t dst, const void* src) {
    asm volatile("cp.async.cg.shared.global [%0], [%1], 16;" :: "r"(dst), "l"(src));
}
__device__ __forceinline__ void cp_async16_zfill(uint32_t dst, const void* src, bool valid) {
    int sz = valid ? 16 : 0;
    asm volatile("cp.async.cg.shared.global [%0], [%1], 16, %2;"
                 :: "r"(dst), "l"(src), "r"(sz));
}
__device__ __forceinline__ void cp_commit() {
    asm volatile("cp.async.commit_group;" ::: "memory");
}
__device__ __forceinline__ void ldmatrix_x4(uint32_t& r0, uint32_t& r1, uint32_t& r2, uint32_t& r3,
                                            uint32_t addr) {
    asm volatile("ldmatrix.sync.aligned.m8n8.x4.shared.b16 {%0,%1,%2,%3}, [%4];"
                 : "=r"(r0), "=r"(r1), "=r"(r2), "=r"(r3) : "r"(addr));
}
__device__ __forceinline__ void mma_16816(float& c0, float& c1, float& c2, float& c3,
                                          uint32_t a0, uint32_t a1, uint32_t a2, uint32_t a3,
                                          uint32_t b0, uint32_t b1) {
    asm volatile(
        "mma.sync.aligned.m16n8k16.row.col.f32.f16.f16.f32 "
        "{%0,%1,%2,%3}, {%4,%5,%6,%7}, {%8,%9}, {%0,%1,%2,%3};"
        : "+f"(c0), "+f"(c1), "+f"(c2), "+f"(c3)
        : "r"(a0), "r"(a1), "r"(a2), "r"(a3), "r"(b0), "r"(b1));
}

// ---------------- Conversion kernels ----------------
// x [B,T,I] f32 -> g_Ah rows [MEFF][IDIM] fp16, row = b*TEFF + t (t < TEFF)
__global__ __launch_bounds__(256) void convert_x_kernel(const float* __restrict__ x) {
    const int row = blockIdx.x;
    const int b = row / TEFF;
    const int t = row - b * TEFF;
    const float4 v = ((const float4*)(x + ((size_t)(b * TLEN + t)) * IDIM))[threadIdx.x];
    __half2 h01 = __float22half2_rn(make_float2(v.x, v.y));
    __half2 h23 = __float22half2_rn(make_float2(v.z, v.w));
    uint2 pk;
    pk.x = *(uint32_t*)&h01;
    pk.y = *(uint32_t*)&h23;
    *(uint2*)(g_Ah + (size_t)row * IDIM + threadIdx.x * 4) = pk;
}

// w [I,O] f32 -> g_Bh [ODIM][IDIM] fp16 (K-major / transposed)
__global__ __launch_bounds__(256) void convert_w_kernel(const float* __restrict__ w) {
    const size_t idx = (size_t)blockIdx.x * 256 + threadIdx.x;  // k*ODIM + n
    const int k = (int)(idx >> 11);
    const int n = (int)(idx & (ODIM - 1));
    g_Bh[(size_t)n * IDIM + k] = __float2half_rn(w[idx]);
}

// ---------------- Fused HMMA GEMM + scan ----------------
// CTA = (n-tile, batch b). Walks t in 4 chunks of <=128 rows; after each
// chunk's GEMM, scans columns in SMEM and writes out[b, t+1, :] directly.
extern __shared__ __half smem[];

__device__ __forceinline__ void load_stage(int tid, int b, int t0, int rows, int n0,
                                           int kidx, int stage, uint32_t sbase) {
    const uint32_t sA = sbase + stage * STAGE_BYTES;
    const uint32_t sB = sA + A_STAGE_HALFS * 2;
    const int k0 = kidx * BK;
#pragma unroll
    for (int q = 0; q < 2; q++) {
        int idx = tid + q * 256;
        int r = idx >> 2, c = idx & 3;               // row 0..127, chunk 0..3 (8 halves)
        bool valid = r < rows;
        int rc = valid ? r : (rows - 1);
        const void* g = (const void*)(g_Ah + (size_t)(b * TEFF + t0 + rc) * IDIM + k0 + c * 8);
        cp_async16_zfill(sA + (r * ROWP + c * 8) * 2, g, valid);
    }
#pragma unroll
    for (int q = 0; q < 2; q++) {
        int idx = tid + q * 256;
        int r = idx >> 2, c = idx & 3;
        const void* g = (const void*)(g_Bh + (size_t)(n0 + r) * IDIM + k0 + c * 8);
        cp_async16(sB + (r * ROWP + c * 8) * 2, g);
    }
}

__global__ __launch_bounds__(256, 2)
void synaptic_fused_kernel(float* __restrict__ out,
                           const float* __restrict__ alpha,
                           const float* __restrict__ beta) {
    const int tid = threadIdx.x;
    const int wid = tid >> 5;
    const int lane = tid & 31;
    const int warp_m = wid & 1;     // 2 warps along M (64 each)
    const int warp_n = wid >> 1;    // 4 warps along N (32 each)
    const int n0 = blockIdx.x * BN;
    const int b  = blockIdx.y;

    const uint32_t sbase = smem_u32(smem);
    float* hs = (float*)smem;       // reused stage smem for h tile (after drain)

    // scan state (threads 0..127, one column each)
    float decay = 0.f, syn = 0.f;
    if (tid < BN) {
        const int o = n0 + tid;
        decay = alpha[o] * (1.0f - beta[o]);
    }

    const int lrow = lane & 15;
    const int lk   = (lane >> 4) * 8;
    const uint32_t a_base = (uint32_t)((warp_m * 64 + lrow) * ROWP + lk) * 2;
    const uint32_t b_base = (uint32_t)((warp_n * 32 + lrow) * ROWP + lk) * 2
                            + (uint32_t)A_STAGE_HALFS * 2;
    const int r_lo = lane >> 2;
    const int c_lo = (lane & 3) * 2;

    for (int ch = 0; ch < NCHUNK; ch++) {
        const int t0 = ch * BM;
        const int rows = (TEFF - t0 < BM) ? (TEFF - t0) : BM;  // 128,128,128,115

        float acc[4][4][4];
#pragma unroll
        for (int i = 0; i < 4; i++)
#pragma unroll
            for (int j = 0; j < 4; j++)
#pragma unroll
                for (int f = 0; f < 4; f++) acc[i][j][f] = 0.f;

        // prologue
#pragma unroll
        for (int s = 0; s < NST - 1; s++) {
            load_stage(tid, b, t0, rows, n0, s, s, sbase);
            cp_commit();
        }

        for (int it = 0; it < NITER; it++) {
            const int s = it & (NST - 1);
            asm volatile("cp.async.wait_group %0;" :: "n"(NST - 2) : "memory");
            __syncthreads();

            if (it + NST - 1 < NITER)
                load_stage(tid, b, t0, rows, n0, it + NST - 1, (it + NST - 1) & (NST - 1), sbase);
            cp_commit();

            const uint32_t sa = sbase + s * STAGE_BYTES + a_base;
            const uint32_t sb = sbase + s * STAGE_BYTES + b_base;

#pragma unroll
            for (int kk = 0; kk < BK; kk += 16) {
                uint32_t a[4][4], bm[2][4];
#pragma unroll
                for (int mt = 0; mt < 4; mt++)
                    ldmatrix_x4(a[mt][0], a[mt][1], a[mt][2], a[mt][3],
                                sa + (mt * 16 * ROWP + kk) * 2);
#pragma unroll
                for (int np = 0; np < 2; np++)
                    ldmatrix_x4(bm[np][0], bm[np][1], bm[np][2], bm[np][3],
                                sb + (np * 16 * ROWP + kk) * 2);
#pragma unroll
                for (int mt = 0; mt < 4; mt++) {
#pragma unroll
                    for (int nt = 0; nt < 4; nt++) {
                        const int np = nt >> 1, odd = nt & 1;
                        mma_16816(acc[mt][nt][0], acc[mt][nt][1], acc[mt][nt][2], acc[mt][nt][3],
                                  a[mt][0], a[mt][1], a[mt][2], a[mt][3],
                                  bm[np][odd], bm[np][2 + odd]);
                    }
                }
            }
            __syncthreads();
        }

        // drain async pipe, then reuse stage smem for the fp32 h tile
        asm volatile("cp.async.wait_group 0;" ::: "memory");
        __syncthreads();

#pragma unroll
        for (int mt = 0; mt < 4; mt++) {
#pragma unroll
            for (int half = 0; half < 2; half++) {
                const int row = warp_m * 64 + mt * 16 + r_lo + half * 8;
                float* dst = hs + (size_t)row * HSTRIDE + warp_n * 32 + c_lo;
#pragma unroll
                for (int nt = 0; nt < 4; nt++) {
                    float2 v;
                    v.x = acc[mt][nt][half * 2 + 0];
                    v.y = acc[mt][nt][half * 2 + 1];
                    *(float2*)(dst + nt * 8) = v;
                }
            }
        }
        __syncthreads();

        // column-parallel scan: thread tid owns column n0+tid
        if (tid < BN) {
            float* obase = out + (size_t)b * TLEN * ODIM + n0 + tid;
            if (ch == 0) obase[0] = 0.0f;   // out[b, 0, :] = 0
#pragma unroll 4
            for (int t = 0; t < rows; t++) {
                float h = hs[(size_t)t * HSTRIDE + tid];
                syn = fmaf(decay, syn, h);
                obase[(size_t)(t0 + t + 1) * ODIM] = syn;
            }
        }
        __syncthreads();   // protect h tile until scan done, before next chunk loads
    }
}

// ---------------- Launch ----------------
extern "C" void kernel_launch(void* const* d_in, const int* in_sizes, int n_in,
                              void* d_out, int out_size) {
    const float* x     = (const float*)d_in[0];
    const float* w     = (const float*)d_in[1];
    const float* alpha = (const float*)d_in[2];
    const float* beta  = (const float*)d_in[3];
    float* out = (float*)d_out;

    cudaFuncSetAttribute(synaptic_fused_kernel, cudaFuncAttributeMaxDynamicSharedMemorySize,
                         SMEM_TOTAL);

    convert_w_kernel<<<(IDIM * ODIM) / 256, 256>>>(w);
    convert_x_kernel<<<MEFF, 256>>>(x);
    synaptic_fused_kernel<<<dim3(ODIM / BN, BATCH), 256, SMEM_TOTAL>>>(out, alpha, beta);
}

// round 6
// speedup vs baseline: 9.8355x; 1.0244x over previous
#include <cuda_runtime.h>
#include <cuda_fp16.h>
#include <cstdint>

// ---------------- Problem constants ----------------
#define BATCH 256
#define TLEN  500
#define IDIM  1024
#define ODIM  2048
#define TEFF  (TLEN - 1)            // 499
#define MEFF  (BATCH * TEFF)

// ---------------- Tiling ----------------
#define BM 128
#define BN 128
#define BK 32
#define NST 4                       // B-pipeline depth (cp.async)
#define NITER (IDIM / BK)           // 32
#define NCHUNK 4                    // ceil(499/128)
#define ROWP  (BK + 8)              // padded row stride in halves (40)
#define ABUF_HALFS (BM * ROWP)      // 5120 per A buffer (fp16, double-buffered)
#define ABUF_BYTES (ABUF_HALFS * 2) // 10240
#define B_STAGE_HALFS (BN * ROWP)   // 5120
#define B_STAGE_BYTES (B_STAGE_HALFS * 2)  // 10240
#define B_BASE_OFF (2 * ABUF_BYTES)        // 20480
#define HSTRIDE 136                 // fp32 h-tile row stride (words)
#define SMEM_TOTAL 71680            // >= max(20480+4*10240, 128*136*4=69632)

// ---------------- Scratch ----------------
__device__ __align__(256) __half g_Bh[(size_t)ODIM * IDIM];  // ~4 MB (L2-resident)

// ---------------- PTX helpers ----------------
__device__ __forceinline__ uint32_t smem_u32(const void* p) {
    uint32_t a;
    asm("{ .reg .u64 t; cvta.to.shared.u64 t, %1; cvt.u32.u64 %0, t; }" : "=r"(a) : "l"(p));
    return a;
}
__device__ __forceinline__ void cp_async16(uint32_t dst, const void* src) {
    asm volatile("cp.async.cg.shared.global [%0], [%1], 16;" :: "r"(dst), "l"(src));
}
__device__ __forceinline__ void cp_commit() {
    asm volatile("cp.async.commit_group;" ::: "memory");
}
__device__ __forceinline__ void sts64(uint32_t addr, uint32_t lo, uint32_t hi) {
    asm volatile("st.shared.v2.u32 [%0], {%1, %2};" :: "r"(addr), "r"(lo), "r"(hi) : "memory");
}
__device__ __forceinline__ void ldmatrix_x4(uint32_t& r0, uint32_t& r1, uint32_t& r2, uint32_t& r3,
                                            uint32_t addr) {
    asm volatile("ldmatrix.sync.aligned.m8n8.x4.shared.b16 {%0,%1,%2,%3}, [%4];"
                 : "=r"(r0), "=r"(r1), "=r"(r2), "=r"(r3) : "r"(addr));
}
__device__ __forceinline__ void mma_16816(float& c0, float& c1, float& c2, float& c3,
                                          uint32_t a0, uint32_t a1, uint32_t a2, uint32_t a3,
                                          uint32_t b0, uint32_t b1) {
    asm volatile(
        "mma.sync.aligned.m16n8k16.row.col.f32.f16.f16.f32 "
        "{%0,%1,%2,%3}, {%4,%5,%6,%7}, {%8,%9}, {%0,%1,%2,%3};"
        : "+f"(c0), "+f"(c1), "+f"(c2), "+f"(c3)
        : "r"(a0), "r"(a1), "r"(a2), "r"(a3), "r"(b0), "r"(b1));
}

// ---------------- w conversion ----------------
// w [I,O] f32 -> g_Bh [ODIM][IDIM] fp16 (K-major / transposed)
__global__ __launch_bounds__(256) void convert_w_kernel(const float* __restrict__ w) {
    const size_t idx = (size_t)blockIdx.x * 256 + threadIdx.x;  // k*ODIM + n
    const int k = (int)(idx >> 11);
    const int n = (int)(idx & (ODIM - 1));
    g_Bh[(size_t)n * IDIM + k] = __float2half_rn(w[idx]);
}

// ---------------- Fused GEMM + scan ----------------
extern __shared__ __half smem[];

// A: predicated LDG.128 of fp32 x into registers (one K-stage: 128x32 fp32)
__device__ __forceinline__ void ldg_a(const float* __restrict__ x, int b, int t0, int rows,
                                      int k0, int tid, float4 (&v)[4]) {
#pragma unroll
    for (int q = 0; q < 4; q++) {
        const int f = q * 256 + tid;
        const int r = f >> 3, c = f & 7;
        float4 t = make_float4(0.f, 0.f, 0.f, 0.f);
        if (r < rows)
            t = *(const float4*)(x + ((size_t)(b * TLEN + t0 + r)) * IDIM + k0 + c * 4);
        v[q] = t;
    }
}
// convert + store to fp16 A buffer
__device__ __forceinline__ void sts_a(uint32_t abuf, int tid, const float4 (&v)[4]) {
#pragma unroll
    for (int q = 0; q < 4; q++) {
        const int f = q * 256 + tid;
        const int r = f >> 3, c = f & 7;
        __half2 h0 = __float22half2_rn(make_float2(v[q].x, v[q].y));
        __half2 h1 = __float22half2_rn(make_float2(v[q].z, v[q].w));
        sts64(abuf + (r * ROWP + c * 4) * 2, *(uint32_t*)&h0, *(uint32_t*)&h1);
    }
}
// B stage load via cp.async
__device__ __forceinline__ void load_b_stage(int tid, int n0, int kidx, int stage,
                                             uint32_t sbase) {
    const uint32_t sB = sbase + B_BASE_OFF + stage * B_STAGE_BYTES;
    const int k0 = kidx * BK;
#pragma unroll
    for (int q = 0; q < 2; q++) {
        int idx = tid + q * 256;
        int r = idx >> 2, c = idx & 3;
        const void* g = (const void*)(g_Bh + (size_t)(n0 + r) * IDIM + k0 + c * 8);
        cp_async16(sB + (r * ROWP + c * 8) * 2, g);
    }
}

__global__ __launch_bounds__(256, 2)
void synaptic_fused_kernel(const float* __restrict__ x,
                           float* __restrict__ out,
                           const float* __restrict__ alpha,
                           const float* __restrict__ beta) {
    const int tid = threadIdx.x;
    const int wid = tid >> 5;
    const int lane = tid & 31;
    const int warp_m = wid & 1;
    const int warp_n = wid >> 1;
    const int n0 = blockIdx.x * BN;
    const int b  = blockIdx.y;

    const uint32_t sbase = smem_u32(smem);
    float* hs = (float*)smem;

    float decay = 0.f, syn = 0.f;
    if (tid < BN) {
        const int o = n0 + tid;
        decay = alpha[o] * (1.0f - beta[o]);
    }

    const int lrow = lane & 15;
    const int lk   = (lane >> 4) * 8;
    const uint32_t a_lane = (uint32_t)((warp_m * 64 + lrow) * ROWP + lk) * 2;
    const uint32_t b_lane = (uint32_t)((warp_n * 32 + lrow) * ROWP + lk) * 2;
    const int r_lo = lane >> 2;
    const int c_lo = (lane & 3) * 2;

    for (int ch = 0; ch < NCHUNK; ch++) {
        const int t0 = ch * BM;
        const int rows = (TEFF - t0 < BM) ? (TEFF - t0) : BM;  // 128,128,128,115

        float acc[4][4][4];
#pragma unroll
        for (int i = 0; i < 4; i++)
#pragma unroll
            for (int j = 0; j < 4; j++)
#pragma unroll
                for (int f = 0; f < 4; f++) acc[i][j][f] = 0.f;

        // ---- prologue ----
        float4 av[4];
        ldg_a(x, b, t0, rows, 0, tid, av);       // A stage 0
        sts_a(sbase, tid, av);                    // -> Abuf[0]
#pragma unroll
        for (int s = 0; s < NST - 1; s++) {       // B stages 0..2
            load_b_stage(tid, n0, s, s, sbase);
            cp_commit();
        }

        for (int it = 0; it < NITER; it++) {
            const int s = it & (NST - 1);
            asm volatile("cp.async.wait_group %0;" :: "n"(NST - 2) : "memory");
            __syncthreads();

            if (it + 1 < NITER)
                ldg_a(x, b, t0, rows, (it + 1) * BK, tid, av);
            if (it + NST - 1 < NITER)
                load_b_stage(tid, n0, it + NST - 1, (it + NST - 1) & (NST - 1), sbase);
            cp_commit();

            const uint32_t sa = sbase + (it & 1) * ABUF_BYTES + a_lane;
            const uint32_t sb = sbase + B_BASE_OFF + s * B_STAGE_BYTES + b_lane;

#pragma unroll
            for (int kk = 0; kk < BK; kk += 16) {
                uint32_t a[4][4], bm[2][4];
#pragma unroll
                for (int mt = 0; mt < 4; mt++)
                    ldmatrix_x4(a[mt][0], a[mt][1], a[mt][2], a[mt][3],
                                sa + (mt * 16 * ROWP + kk) * 2);
#pragma unroll
                for (int np = 0; np < 2; np++)
                    ldmatrix_x4(bm[np][0], bm[np][1], bm[np][2], bm[np][3],
                                sb + (np * 16 * ROWP + kk) * 2);
#pragma unroll
                for (int mt = 0; mt < 4; mt++) {
#pragma unroll
                    for (int nt = 0; nt < 4; nt++) {
                        const int np = nt >> 1, odd = nt & 1;
                        mma_16816(acc[mt][nt][0], acc[mt][nt][1], acc[mt][nt][2], acc[mt][nt][3],
                                  a[mt][0], a[mt][1], a[mt][2], a[mt][3],
                                  bm[np][odd], bm[np][2 + odd]);
                    }
                }
            }

            // convert+store next A stage (visible after next iteration's barrier)
            if (it + 1 < NITER)
                sts_a(sbase + ((it + 1) & 1) * ABUF_BYTES, tid, av);
            __syncthreads();
        }

        // drain B pipe, reuse smem for fp32 h tile
        asm volatile("cp.async.wait_group 0;" ::: "memory");
        __syncthreads();

#pragma unroll
        for (int mt = 0; mt < 4; mt++) {
#pragma unroll
            for (int half = 0; half < 2; half++) {
                const int row = warp_m * 64 + mt * 16 + r_lo + half * 8;
                float* dst = hs + (size_t)row * HSTRIDE + warp_n * 32 + c_lo;
#pragma unroll
                for (int nt = 0; nt < 4; nt++) {
                    float2 v;
                    v.x = acc[mt][nt][half * 2 + 0];
                    v.y = acc[mt][nt][half * 2 + 1];
                    *(float2*)(dst + nt * 8) = v;
                }
            }
        }
        __syncthreads();

        // column-parallel scan
        if (tid < BN) {
            float* obase = out + (size_t)b * TLEN * ODIM + n0 + tid;
            if (ch == 0) obase[0] = 0.0f;
#pragma unroll 4
            for (int t = 0; t < rows; t++) {
                float h = hs[(size_t)t * HSTRIDE + tid];
                syn = fmaf(decay, syn, h);
                obase[(size_t)(t0 + t + 1) * ODIM] = syn;
            }
        }
        __syncthreads();
    }
}

// ---------------- Launch ----------------
extern "C" void kernel_launch(void* const* d_in, const int* in_sizes, int n_in,
                              void* d_out, int out_size) {
    const float* x     = (const float*)d_in[0];
    const float* w     = (const float*)d_in[1];
    const float* alpha = (const float*)d_in[2];
    const float* beta  = (const float*)d_in[3];
    float* out = (float*)d_out;

    cudaFuncSetAttribute(synaptic_fused_kernel, cudaFuncAttributeMaxDynamicSharedMemorySize,
                         SMEM_TOTAL);

    convert_w_kernel<<<(IDIM * ODIM) / 256, 256>>>(w);
    synaptic_fused_kernel<<<dim3(ODIM / BN, BATCH), 256, SMEM_TOTAL>>>(x, out, alpha, beta);
}

// round 7
// speedup vs baseline: 9.8516x; 1.0016x over previous
#include <cuda_runtime.h>
#include <cuda_fp16.h>
#include <cstdint>

// ---------------- Problem constants ----------------
#define BATCH 256
#define TLEN  500
#define IDIM  1024
#define ODIM  2048
#define TEFF  (TLEN - 1)            // 499
#define MEFF  (BATCH * TEFF)

// ---------------- Tiling ----------------
#define BM 128
#define BN 128
#define BK 32
#define NST 4                       // B-pipeline depth (cp.async)
#define NITER (IDIM / BK)           // 32
#define NCHUNK 4                    // ceil(499/128)
#define ROWP  (BK + 8)              // padded row stride in halves (40)
#define ABUF_HALFS (BM * ROWP)      // 5120 per A buffer (fp16, double-buffered)
#define ABUF_BYTES (ABUF_HALFS * 2) // 10240
#define B_STAGE_BYTES (BN * ROWP * 2)      // 10240
#define B_BASE_OFF (2 * ABUF_BYTES)        // 20480
#define H_OFF   (B_BASE_OFF + NST * B_STAGE_BYTES)  // 61440
#define ROWPH 136                   // h-tile row stride in halves
#define SMEM_TOTAL (H_OFF + BM * ROWPH * 2)         // 96256

// ---------------- Scratch ----------------
__device__ __align__(256) __half g_Bh[(size_t)ODIM * IDIM];  // ~4 MB (L2-resident)

// ---------------- PTX helpers ----------------
__device__ __forceinline__ uint32_t smem_u32(const void* p) {
    uint32_t a;
    asm("{ .reg .u64 t; cvta.to.shared.u64 t, %1; cvt.u32.u64 %0, t; }" : "=r"(a) : "l"(p));
    return a;
}
__device__ __forceinline__ void cp_async16(uint32_t dst, const void* src) {
    asm volatile("cp.async.cg.shared.global [%0], [%1], 16;" :: "r"(dst), "l"(src));
}
__device__ __forceinline__ void cp_commit() {
    asm volatile("cp.async.commit_group;" ::: "memory");
}
__device__ __forceinline__ void sts64(uint32_t addr, uint32_t lo, uint32_t hi) {
    asm volatile("st.shared.v2.u32 [%0], {%1, %2};" :: "r"(addr), "r"(lo), "r"(hi) : "memory");
}
__device__ __forceinline__ void ldmatrix_x4(uint32_t& r0, uint32_t& r1, uint32_t& r2, uint32_t& r3,
                                            uint32_t addr) {
    asm volatile("ldmatrix.sync.aligned.m8n8.x4.shared.b16 {%0,%1,%2,%3}, [%4];"
                 : "=r"(r0), "=r"(r1), "=r"(r2), "=r"(r3) : "r"(addr));
}
__device__ __forceinline__ void mma_16816(float& c0, float& c1, float& c2, float& c3,
                                          uint32_t a0, uint32_t a1, uint32_t a2, uint32_t a3,
                                          uint32_t b0, uint32_t b1) {
    asm volatile(
        "mma.sync.aligned.m16n8k16.row.col.f32.f16.f16.f32 "
        "{%0,%1,%2,%3}, {%4,%5,%6,%7}, {%8,%9}, {%0,%1,%2,%3};"
        : "+f"(c0), "+f"(c1), "+f"(c2), "+f"(c3)
        : "r"(a0), "r"(a1), "r"(a2), "r"(a3), "r"(b0), "r"(b1));
}

// ---------------- w conversion ----------------
__global__ __launch_bounds__(256) void convert_w_kernel(const float* __restrict__ w) {
    const size_t idx = (size_t)blockIdx.x * 256 + threadIdx.x;  // k*ODIM + n
    const int k = (int)(idx >> 11);
    const int n = (int)(idx & (ODIM - 1));
    g_Bh[(size_t)n * IDIM + k] = __float2half_rn(w[idx]);
}

// ---------------- Fused GEMM + scan ----------------
extern __shared__ __half smem[];

__device__ __forceinline__ void ldg_a(const float* __restrict__ x, int b, int t0, int rows,
                                      int k0, int tid, float4 (&v)[4]) {
#pragma unroll
    for (int q = 0; q < 4; q++) {
        const int f = q * 256 + tid;
        const int r = f >> 3, c = f & 7;
        float4 t = make_float4(0.f, 0.f, 0.f, 0.f);
        if (r < rows)
            t = *(const float4*)(x + ((size_t)(b * TLEN + t0 + r)) * IDIM + k0 + c * 4);
        v[q] = t;
    }
}
__device__ __forceinline__ void sts_a(uint32_t abuf, int tid, const float4 (&v)[4]) {
#pragma unroll
    for (int q = 0; q < 4; q++) {
        const int f = q * 256 + tid;
        const int r = f >> 3, c = f & 7;
        __half2 h0 = __float22half2_rn(make_float2(v[q].x, v[q].y));
        __half2 h1 = __float22half2_rn(make_float2(v[q].z, v[q].w));
        sts64(abuf + (r * ROWP + c * 4) * 2, *(uint32_t*)&h0, *(uint32_t*)&h1);
    }
}
__device__ __forceinline__ void load_b_stage(int tid, int n0, int kidx, int stage,
                                             uint32_t sbase) {
    const uint32_t sB = sbase + B_BASE_OFF + stage * B_STAGE_BYTES;
    const int k0 = kidx * BK;
#pragma unroll
    for (int q = 0; q < 2; q++) {
        int idx = tid + q * 256;
        int r = idx >> 2, c = idx & 3;
        const void* g = (const void*)(g_Bh + (size_t)(n0 + r) * IDIM + k0 + c * 8);
        cp_async16(sB + (r * ROWP + c * 8) * 2, g);
    }
}

__global__ __launch_bounds__(256, 2)
void synaptic_fused_kernel(const float* __restrict__ x,
                           float* __restrict__ out,
                           const float* __restrict__ alpha,
                           const float* __restrict__ beta) {
    const int tid = threadIdx.x;
    const int wid = tid >> 5;
    const int lane = tid & 31;
    const int warp_m = wid & 1;
    const int warp_n = wid >> 1;
    const int n0 = blockIdx.x * BN;
    const int b  = blockIdx.y;

    const uint32_t sbase = smem_u32(smem);
    __half* hs16 = (__half*)((char*)smem + H_OFF);

    float decay = 0.f, syn = 0.f;
    if (tid < BN) {
        const int o = n0 + tid;
        decay = alpha[o] * (1.0f - beta[o]);
    }

    const int lrow = lane & 15;
    const int lk   = (lane >> 4) * 8;
    const uint32_t a_lane = (uint32_t)((warp_m * 64 + lrow) * ROWP + lk) * 2;
    const uint32_t b_lane = (uint32_t)((warp_n * 32 + lrow) * ROWP + lk) * 2;
    const int r_lo = lane >> 2;
    const int c_lo = (lane & 3) * 2;

    float4 av[4];

    // ---- prologue for chunk 0 ----
    ldg_a(x, b, 0, BM, 0, tid, av);
    sts_a(sbase, tid, av);
#pragma unroll
    for (int s = 0; s < NST - 1; s++) {
        load_b_stage(tid, n0, s, s, sbase);
        cp_commit();
    }

    for (int ch = 0; ch < NCHUNK; ch++) {
        const int t0 = ch * BM;
        const int rows = (TEFF - t0 < BM) ? (TEFF - t0) : BM;  // 128,128,128,115

        float acc[4][4][4];
#pragma unroll
        for (int i = 0; i < 4; i++)
#pragma unroll
            for (int j = 0; j < 4; j++)
#pragma unroll
                for (int f = 0; f < 4; f++) acc[i][j][f] = 0.f;

        // ---- mainloop: ONE barrier per iteration ----
        for (int it = 0; it < NITER; it++) {
            const int s = it & (NST - 1);
            asm volatile("cp.async.wait_group %0;" :: "n"(NST - 2) : "memory");
            __syncthreads();

            if (it + 1 < NITER)
                ldg_a(x, b, t0, rows, (it + 1) * BK, tid, av);
            if (it + NST - 1 < NITER)
                load_b_stage(tid, n0, it + NST - 1, (it + NST - 1) & (NST - 1), sbase);
            cp_commit();

            const uint32_t sa = sbase + (it & 1) * ABUF_BYTES + a_lane;
            const uint32_t sb = sbase + B_BASE_OFF + s * B_STAGE_BYTES + b_lane;

#pragma unroll
            for (int kk = 0; kk < BK; kk += 16) {
                uint32_t a[4][4], bm[2][4];
#pragma unroll
                for (int mt = 0; mt < 4; mt++)
                    ldmatrix_x4(a[mt][0], a[mt][1], a[mt][2], a[mt][3],
                                sa + (mt * 16 * ROWP + kk) * 2);
#pragma unroll
                for (int np = 0; np < 2; np++)
                    ldmatrix_x4(bm[np][0], bm[np][1], bm[np][2], bm[np][3],
                                sb + (np * 16 * ROWP + kk) * 2);
#pragma unroll
                for (int mt = 0; mt < 4; mt++) {
#pragma unroll
                    for (int nt = 0; nt < 4; nt++) {
                        const int np = nt >> 1, odd = nt & 1;
                        mma_16816(acc[mt][nt][0], acc[mt][nt][1], acc[mt][nt][2], acc[mt][nt][3],
                                  a[mt][0], a[mt][1], a[mt][2], a[mt][3],
                                  bm[np][odd], bm[np][2 + odd]);
                    }
                }
            }

            if (it + 1 < NITER)
                sts_a(sbase + ((it + 1) & 1) * ABUF_BYTES, tid, av);
        }

        // ---- write h tile (fp16) to dedicated smem; no pipeline drain needed ----
#pragma unroll
        for (int mt = 0; mt < 4; mt++) {
#pragma unroll
            for (int half = 0; half < 2; half++) {
                const int row = warp_m * 64 + mt * 16 + r_lo + half * 8;
                __half* dst = hs16 + (size_t)row * ROWPH + warp_n * 32 + c_lo;
#pragma unroll
                for (int nt = 0; nt < 4; nt++) {
                    __half2 hv = __float22half2_rn(
                        make_float2(acc[mt][nt][half * 2 + 0], acc[mt][nt][half * 2 + 1]));
                    *(__half2*)(dst + nt * 8) = hv;
                }
            }
        }
        __syncthreads();   // h visible; pipeline buffers now free for next chunk

        // ---- issue next chunk's prologue BEFORE the scan (overlap DMA with scan) ----
        if (ch + 1 < NCHUNK) {
            const int nt0 = (ch + 1) * BM;
            const int nrows = (TEFF - nt0 < BM) ? (TEFF - nt0) : BM;
            ldg_a(x, b, nt0, nrows, 0, tid, av);
            sts_a(sbase, tid, av);
#pragma unroll
            for (int s = 0; s < NST - 1; s++) {
                load_b_stage(tid, n0, s, s, sbase);
                cp_commit();
            }
        }

        // ---- column-parallel scan (warps 0-3); others park at next barrier ----
        if (tid < BN) {
            float* obase = out + (size_t)b * TLEN * ODIM + n0 + tid;
            if (ch == 0) obase[0] = 0.0f;
#pragma unroll 4
            for (int t = 0; t < rows; t++) {
                float h = __half2float(hs16[(size_t)t * ROWPH + tid]);
                syn = fmaf(decay, syn, h);
                obase[(size_t)(t0 + t + 1) * ODIM] = syn;
            }
        }
        // no trailing barrier: next chunk's mainloop top barrier orders everything
    }
}

// ---------------- Launch ----------------
extern "C" void kernel_launch(void* const* d_in, const int* in_sizes, int n_in,
                              void* d_out, int out_size) {
    const float* x     = (const float*)d_in[0];
    const float* w     = (const float*)d_in[1];
    const float* alpha = (const float*)d_in[2];
    const float* beta  = (const float*)d_in[3];
    float* out = (float*)d_out;

    cudaFuncSetAttribute(synaptic_fused_kernel, cudaFuncAttributeMaxDynamicSharedMemorySize,
                         SMEM_TOTAL);

    convert_w_kernel<<<(IDIM * ODIM) / 256, 256>>>(w);
    synaptic_fused_kernel<<<dim3(ODIM / BN, BATCH), 256, SMEM_TOTAL>>>(x, out, alpha, beta);
}